// round 3
// baseline (speedup 1.0000x reference)
#include <cuda_runtime.h>
#include <cuda_bf16.h>

#define N_NODES    100000
#define N_EDGES    1600000
#define F_IN       100
#define HEADS      3
#define HEAD_DIM   64
#define HIDDEN     192
#define NUM_GRAPHS 128
#define NUM_CLASSES 2
#define SLOPE_ATT  0.2f
#define SLOPE_ACT  0.01f

#define SCAN_NB    ((N_NODES + 1023) / 1024)   // 98

// ---------------- scratch (static __device__: allocation-free) ----------------
__device__ float        g_h[N_NODES * HIDDEN];        // 76.8 MB
__device__ float        g_asrc[N_NODES * HEADS];
__device__ float        g_adst[N_NODES * HEADS];
__device__ int          g_deg[N_NODES];
__device__ int          g_row[N_NODES];               // exclusive prefix of deg
__device__ int          g_cur[N_NODES];
__device__ int          g_esrc[N_EDGES];              // CSR: src list grouped by dst
__device__ unsigned     g_pool[NUM_GRAPHS * HIDDEN];  // encoded-float max
__device__ int          g_part[128];                  // scan partials

// ---------------- helpers ----------------
__device__ __forceinline__ float lrelu(float x, float s) { return x > 0.f ? x : s * x; }

__device__ __forceinline__ unsigned enc_f(float f) {
    unsigned b = __float_as_uint(f);
    return (b & 0x80000000u) ? ~b : (b | 0x80000000u);
}
__device__ __forceinline__ float dec_f(unsigned k) {
    unsigned b = (k & 0x80000000u) ? (k & 0x7FFFFFFFu) : ~k;
    return __uint_as_float(b);
}

// packed f32x2 FMA (Blackwell PTX-only; 2x fp32 throughput)
__device__ __forceinline__ unsigned long long ffma2(unsigned long long a,
                                                    unsigned long long b,
                                                    unsigned long long c) {
    unsigned long long d;
    asm("fma.rn.f32x2 %0, %1, %2, %3;" : "=l"(d) : "l"(a), "l"(b), "l"(c));
    return d;
}
__device__ __forceinline__ unsigned long long packdup(float x) {
    unsigned long long r;
    asm("mov.b64 %0, {%1, %1};" : "=l"(r) : "f"(x));
    return r;
}
__device__ __forceinline__ float2 unpack2(unsigned long long v) {
    float2 r;
    asm("mov.b64 {%0, %1}, %2;" : "=f"(r.x), "=f"(r.y) : "l"(v));
    return r;
}

__device__ __forceinline__ int warp_iscan(int v, int lane) {
    #pragma unroll
    for (int d = 1; d < 32; d <<= 1) {
        int t = __shfl_up_sync(0xFFFFFFFFu, v, d);
        if (lane >= d) v += t;
    }
    return v;
}

// ---------------- 0: init scratch ----------------
__global__ void init_kernel() {
    int stride = gridDim.x * blockDim.x;
    for (int i = blockIdx.x * blockDim.x + threadIdx.x; i < N_NODES; i += stride) {
        g_deg[i] = 0;
        g_cur[i] = 0;
    }
    for (int i = blockIdx.x * blockDim.x + threadIdx.x; i < NUM_GRAPHS * HIDDEN; i += stride)
        g_pool[i] = 0u;   // encodes "most negative"
}

// ---------------- 1: h = x @ W  (fp32, packed f32x2, static smem <=48KB) ----------------
// 32 rows x 192 cols per block, K split in two 50-wide phases.
#define GEMM_T 192
#define GEMM_R 32
#define KHALF  50
__global__ __launch_bounds__(GEMM_T)
void gemm_kernel(const float* __restrict__ x, const float* __restrict__ W) {
    __shared__ unsigned long long sW[KHALF * 96];   // 38400 B (96 col-pairs)
    __shared__ float sX[GEMM_R * KHALF];            //  6400 B

    int tid = threadIdx.x;
    int rowbase = blockIdx.x * GEMM_R;
    int rs = tid & 3;           // row slot 0..3 -> rows rs + 4i
    int pc = tid >> 2;          // pair-group 0..47 -> pairs pc*2, pc*2+1

    unsigned long long acc[8][2];
    #pragma unroll
    for (int i = 0; i < 8; i++) { acc[i][0] = 0ull; acc[i][1] = 0ull; }

    const float2* W2 = (const float2*)W;   // [100][96] pairs
    const float2* x2 = (const float2*)x;

    #pragma unroll 1
    for (int ph = 0; ph < 2; ph++) {
        int k0 = ph * KHALF;
        __syncthreads();
        for (int i = tid; i < KHALF * 96; i += GEMM_T) {
            int k = i / 96, p = i % 96;
            float2 v = W2[(k0 + k) * 96 + p];
            unsigned long long q;
            asm("mov.b64 %0, {%1, %2};" : "=l"(q) : "f"(v.x), "f"(v.y));
            sW[i] = q;
        }
        float2* sX2 = (float2*)sX;
        for (int i = tid; i < GEMM_R * (KHALF / 2); i += GEMM_T) {
            int r = i / 25, j = i % 25;
            sX2[r * 25 + j] = x2[(long long)(rowbase + r) * 50 + ph * 25 + j];
        }
        __syncthreads();

        #pragma unroll 2
        for (int k = 0; k < KHALF; k++) {
            unsigned long long w0 = sW[k * 96 + pc * 2];
            unsigned long long w1 = sW[k * 96 + pc * 2 + 1];
            #pragma unroll
            for (int i = 0; i < 8; i++) {
                unsigned long long xx = packdup(sX[(rs + 4 * i) * KHALF + k]);
                acc[i][0] = ffma2(xx, w0, acc[i][0]);
                acc[i][1] = ffma2(xx, w1, acc[i][1]);
            }
        }
    }

    #pragma unroll
    for (int i = 0; i < 8; i++) {
        int r = rowbase + rs + 4 * i;      // grid exactly covers N_NODES (3125*32)
        float2* o = (float2*)(g_h + (long long)r * HIDDEN);
        o[pc * 2]     = unpack2(acc[i][0]);
        o[pc * 2 + 1] = unpack2(acc[i][1]);
    }
}

// ---------------- 2: attention logits a_src/a_dst (warp per node) ----------------
__global__ void adot_kernel(const float* __restrict__ att_src,
                            const float* __restrict__ att_dst) {
    int lane = threadIdx.x & 31;
    int n = blockIdx.x * (blockDim.x >> 5) + (threadIdx.x >> 5);
    if (n >= N_NODES) return;

    const float2* hp = (const float2*)(g_h + (long long)n * HIDDEN);
    const float2* as2 = (const float2*)att_src;
    const float2* ad2 = (const float2*)att_dst;

    float ps[HEADS], pd[HEADS];
    #pragma unroll
    for (int h = 0; h < HEADS; h++) {
        float2 v = hp[h * 32 + lane];
        float2 a = as2[h * 32 + lane];
        float2 b = ad2[h * 32 + lane];
        ps[h] = v.x * a.x + v.y * a.y;
        pd[h] = v.x * b.x + v.y * b.y;
    }
    #pragma unroll
    for (int d = 16; d > 0; d >>= 1) {
        #pragma unroll
        for (int h = 0; h < HEADS; h++) {
            ps[h] += __shfl_xor_sync(0xFFFFFFFFu, ps[h], d);
            pd[h] += __shfl_xor_sync(0xFFFFFFFFu, pd[h], d);
        }
    }
    if (lane == 0) {
        #pragma unroll
        for (int h = 0; h < HEADS; h++) {
            g_asrc[n * HEADS + h] = ps[h];
            g_adst[n * HEADS + h] = pd[h];
        }
    }
}

// ---------------- 3: degree histogram (edge_index is int32!) ----------------
__global__ void hist_kernel(const int* __restrict__ ei) {
    int i = blockIdx.x * blockDim.x + threadIdx.x;
    if (i >= N_EDGES) return;
    atomicAdd(&g_deg[ei[N_EDGES + i]], 1);
}

// ---------------- 4: exclusive scan of deg -> row offsets ----------------
__global__ void scan_blocks() {
    __shared__ int ws[32];
    int tid = threadIdx.x, lane = tid & 31, w = tid >> 5;
    int i = blockIdx.x * 1024 + tid;
    int v = (i < N_NODES) ? g_deg[i] : 0;
    int inc = warp_iscan(v, lane);
    if (lane == 31) ws[w] = inc;
    __syncthreads();
    if (w == 0) ws[lane] = warp_iscan(ws[lane], lane);
    __syncthreads();
    int base = (w > 0) ? ws[w - 1] : 0;
    if (i < N_NODES) g_row[i] = base + inc - v;
    if (tid == 0) g_part[blockIdx.x] = ws[31];
}
__global__ void scan_part() {
    __shared__ int ws[4];
    int t = threadIdx.x, lane = t & 31, w = t >> 5;
    int v = (t < SCAN_NB) ? g_part[t] : 0;
    int inc = warp_iscan(v, lane);
    if (lane == 31) ws[w] = inc;
    __syncthreads();
    if (w == 0 && lane < 4) {
        int s = ws[lane];
        #pragma unroll
        for (int d = 1; d < 4; d <<= 1) {
            int tt = __shfl_up_sync(0x0000000Fu, s, d);
            if (lane >= d) s += tt;
        }
        ws[lane] = s;
    }
    __syncthreads();
    int base = (w > 0) ? ws[w - 1] : 0;
    if (t < SCAN_NB) g_part[t] = base + inc - v;
}
__global__ void scan_add() {
    int i = blockIdx.x * 1024 + threadIdx.x;
    if (i < N_NODES) g_row[i] += g_part[blockIdx.x];
}

// ---------------- 5: scatter edges into CSR by dst ----------------
__global__ void scatter_kernel(const int* __restrict__ ei) {
    int i = blockIdx.x * blockDim.x + threadIdx.x;
    if (i >= N_EDGES) return;
    int s = ei[i];
    int d = ei[N_EDGES + i];
    int pos = g_row[d] + atomicAdd(&g_cur[d], 1);
    g_esrc[pos] = s;
}

// ---------------- 6: softmax-attention aggregation + pooling (warp/node) ----------------
__global__ void aggregate_kernel(const int* __restrict__ batch,
                                 const float* __restrict__ bias) {
    int lane = threadIdx.x & 31;
    int n = blockIdx.x * (blockDim.x >> 5) + (threadIdx.x >> 5);
    if (n >= N_NODES) return;

    int start = g_row[n];
    int deg   = g_deg[n];

    float ad0 = g_adst[n * 3 + 0], ad1 = g_adst[n * 3 + 1], ad2 = g_adst[n * 3 + 2];
    float es0 = lrelu(g_asrc[n * 3 + 0] + ad0, SLOPE_ATT);
    float es1 = lrelu(g_asrc[n * 3 + 1] + ad1, SLOPE_ATT);
    float es2 = lrelu(g_asrc[n * 3 + 2] + ad2, SLOPE_ATT);

    // pass 1: segment max (lane-parallel over edges, self-loop included)
    float m0 = es0, m1 = es1, m2 = es2;
    for (int j = lane; j < deg; j += 32) {
        int s = g_esrc[start + j];
        m0 = fmaxf(m0, lrelu(g_asrc[s * 3 + 0] + ad0, SLOPE_ATT));
        m1 = fmaxf(m1, lrelu(g_asrc[s * 3 + 1] + ad1, SLOPE_ATT));
        m2 = fmaxf(m2, lrelu(g_asrc[s * 3 + 2] + ad2, SLOPE_ATT));
    }
    #pragma unroll
    for (int d = 16; d > 0; d >>= 1) {
        m0 = fmaxf(m0, __shfl_xor_sync(0xFFFFFFFFu, m0, d));
        m1 = fmaxf(m1, __shfl_xor_sync(0xFFFFFFFFu, m1, d));
        m2 = fmaxf(m2, __shfl_xor_sync(0xFFFFFFFFu, m2, d));
    }

    // pass 2: weighted gather (warp-sequential edges; lane owns 2 feats/head)
    float w0 = __expf(es0 - m0), w1 = __expf(es1 - m1), w2 = __expf(es2 - m2);
    float den0 = w0, den1 = w1, den2 = w2;
    const float2* hp = (const float2*)(g_h + (long long)n * HIDDEN);
    float2 v0 = hp[lane], v1 = hp[32 + lane], v2 = hp[64 + lane];
    float2 a0 = make_float2(w0 * v0.x, w0 * v0.y);
    float2 a1 = make_float2(w1 * v1.x, w1 * v1.y);
    float2 a2 = make_float2(w2 * v2.x, w2 * v2.y);

    for (int j = 0; j < deg; j++) {
        int s = g_esrc[start + j];                 // broadcast
        float e0 = lrelu(g_asrc[s * 3 + 0] + ad0, SLOPE_ATT);
        float e1 = lrelu(g_asrc[s * 3 + 1] + ad1, SLOPE_ATT);
        float e2 = lrelu(g_asrc[s * 3 + 2] + ad2, SLOPE_ATT);
        float x0 = __expf(e0 - m0), x1 = __expf(e1 - m1), x2 = __expf(e2 - m2);
        den0 += x0; den1 += x1; den2 += x2;
        const float2* sp = (const float2*)(g_h + (long long)s * HIDDEN);
        float2 u0 = sp[lane], u1 = sp[32 + lane], u2 = sp[64 + lane];
        a0.x += x0 * u0.x; a0.y += x0 * u0.y;
        a1.x += x1 * u1.x; a1.y += x1 * u1.y;
        a2.x += x2 * u2.x; a2.y += x2 * u2.y;
    }

    int g = batch[n];
    const float2* b2 = (const float2*)bias;
    float2 bb0 = b2[lane], bb1 = b2[32 + lane], bb2 = b2[64 + lane];

    float o;
    unsigned* pool = g_pool + g * HIDDEN;
    o = lrelu(a0.x / den0 + bb0.x, SLOPE_ACT); atomicMax(&pool[       lane * 2    ], enc_f(o));
    o = lrelu(a0.y / den0 + bb0.y, SLOPE_ACT); atomicMax(&pool[       lane * 2 + 1], enc_f(o));
    o = lrelu(a1.x / den1 + bb1.x, SLOPE_ACT); atomicMax(&pool[ 64 +  lane * 2    ], enc_f(o));
    o = lrelu(a1.y / den1 + bb1.y, SLOPE_ACT); atomicMax(&pool[ 64 +  lane * 2 + 1], enc_f(o));
    o = lrelu(a2.x / den2 + bb2.x, SLOPE_ACT); atomicMax(&pool[128 +  lane * 2    ], enc_f(o));
    o = lrelu(a2.y / den2 + bb2.y, SLOPE_ACT); atomicMax(&pool[128 +  lane * 2 + 1], enc_f(o));
}

// ---------------- 7: classifier ----------------
__global__ void classify_kernel(const float* __restrict__ clsW,
                                const float* __restrict__ clsb,
                                float* __restrict__ out) {
    int t = threadIdx.x;
    if (t >= NUM_GRAPHS * NUM_CLASSES) return;
    int g = t >> 1, c = t & 1;
    float s = clsb[c];
    #pragma unroll 4
    for (int k = 0; k < HIDDEN; k++)
        s += dec_f(g_pool[g * HIDDEN + k]) * clsW[k * NUM_CLASSES + c];
    out[g * NUM_CLASSES + c] = s;
}

// ---------------- launch ----------------
extern "C" void kernel_launch(void* const* d_in, const int* in_sizes, int n_in,
                              void* d_out, int out_size) {
    const float* x       = (const float*)d_in[0];
    const int*   ei      = (const int*)d_in[1];     // int32 (JAX x64 disabled)
    const int*   batch   = (const int*)d_in[2];     // int32
    const float* W       = (const float*)d_in[3];
    const float* att_src = (const float*)d_in[4];
    const float* att_dst = (const float*)d_in[5];
    const float* bias    = (const float*)d_in[6];
    const float* clsW    = (const float*)d_in[7];
    const float* clsb    = (const float*)d_in[8];
    float* out = (float*)d_out;

    init_kernel<<<256, 256>>>();
    gemm_kernel<<<N_NODES / GEMM_R, GEMM_T>>>(x, W);
    adot_kernel<<<(N_NODES + 7) / 8, 256>>>(att_src, att_dst);
    hist_kernel<<<(N_EDGES + 255) / 256, 256>>>(ei);
    scan_blocks<<<SCAN_NB, 1024>>>();
    scan_part<<<1, 128>>>();
    scan_add<<<SCAN_NB, 1024>>>();
    scatter_kernel<<<(N_EDGES + 255) / 256, 256>>>(ei);
    aggregate_kernel<<<(N_NODES + 7) / 8, 256>>>(batch, bias);
    classify_kernel<<<1, 256>>>(clsW, clsb, out);
}

// round 10
// speedup vs baseline: 1.2823x; 1.2823x over previous
#include <cuda_runtime.h>
#include <cuda_bf16.h>

#define N_NODES    100000
#define N_EDGES    1600000
#define F_IN       100
#define HEADS      3
#define HEAD_DIM   64
#define HIDDEN     192
#define NUM_GRAPHS 128
#define NUM_CLASSES 2
#define SLOPE_ATT  0.2f
#define SLOPE_ACT  0.01f

#define SCAN_NB    ((N_NODES + 1023) / 1024)   // 98

// ---------------- scratch (static __device__: allocation-free) ----------------
__device__ float        g_h[N_NODES * HIDDEN];        // 76.8 MB
__device__ float        g_asrc[N_NODES * HEADS];
__device__ float        g_adst[N_NODES * HEADS];
__device__ int          g_deg[N_NODES];
__device__ int          g_row[N_NODES];               // exclusive prefix of deg
__device__ int          g_cur[N_NODES];
__device__ int4         g_epack[N_EDGES];             // CSR: {src, w0,w1,w2 bits}
__device__ unsigned     g_pool[NUM_GRAPHS * HIDDEN];  // encoded-float max
__device__ int          g_part[128];                  // scan partials

// ---------------- helpers ----------------
__device__ __forceinline__ float lrelu(float x, float s) { return x > 0.f ? x : s * x; }

__device__ __forceinline__ unsigned enc_f(float f) {
    unsigned b = __float_as_uint(f);
    return (b & 0x80000000u) ? ~b : (b | 0x80000000u);
}
__device__ __forceinline__ float dec_f(unsigned k) {
    unsigned b = (k & 0x80000000u) ? (k & 0x7FFFFFFFu) : ~k;
    return __uint_as_float(b);
}

// packed f32x2 FMA (Blackwell PTX-only; 2x fp32 throughput)
__device__ __forceinline__ unsigned long long ffma2(unsigned long long a,
                                                    unsigned long long b,
                                                    unsigned long long c) {
    unsigned long long d;
    asm("fma.rn.f32x2 %0, %1, %2, %3;" : "=l"(d) : "l"(a), "l"(b), "l"(c));
    return d;
}
__device__ __forceinline__ unsigned long long packdup(float x) {
    unsigned long long r;
    asm("mov.b64 %0, {%1, %1};" : "=l"(r) : "f"(x));
    return r;
}
__device__ __forceinline__ float2 unpack2(unsigned long long v) {
    float2 r;
    asm("mov.b64 {%0, %1}, %2;" : "=f"(r.x), "=f"(r.y) : "l"(v));
    return r;
}

__device__ __forceinline__ int warp_iscan(int v, int lane) {
    #pragma unroll
    for (int d = 1; d < 32; d <<= 1) {
        int t = __shfl_up_sync(0xFFFFFFFFu, v, d);
        if (lane >= d) v += t;
    }
    return v;
}

// ---------------- 0: init scratch ----------------
__global__ void init_kernel() {
    int stride = gridDim.x * blockDim.x;
    for (int i = blockIdx.x * blockDim.x + threadIdx.x; i < N_NODES; i += stride) {
        g_deg[i] = 0;
        g_cur[i] = 0;
    }
    for (int i = blockIdx.x * blockDim.x + threadIdx.x; i < NUM_GRAPHS * HIDDEN; i += stride)
        g_pool[i] = 0u;   // encodes "most negative"
}

// ---------------- 1: h = x @ W  (fp32, packed f32x2, static smem <=48KB) ----------------
#define GEMM_T 192
#define GEMM_R 32
#define KHALF  50
__global__ __launch_bounds__(GEMM_T)
void gemm_kernel(const float* __restrict__ x, const float* __restrict__ W) {
    __shared__ unsigned long long sW[KHALF * 96];   // 38400 B (96 col-pairs)
    __shared__ float sX[GEMM_R * KHALF];            //  6400 B

    int tid = threadIdx.x;
    int rowbase = blockIdx.x * GEMM_R;
    int rs = tid & 3;           // row slot 0..3 -> rows rs + 4i
    int pc = tid >> 2;          // pair-group 0..47 -> pairs pc*2, pc*2+1

    unsigned long long acc[8][2];
    #pragma unroll
    for (int i = 0; i < 8; i++) { acc[i][0] = 0ull; acc[i][1] = 0ull; }

    const float2* W2 = (const float2*)W;   // [100][96] pairs
    const float2* x2 = (const float2*)x;

    #pragma unroll 1
    for (int ph = 0; ph < 2; ph++) {
        int k0 = ph * KHALF;
        __syncthreads();
        for (int i = tid; i < KHALF * 96; i += GEMM_T) {
            int k = i / 96, p = i % 96;
            float2 v = W2[(k0 + k) * 96 + p];
            unsigned long long q;
            asm("mov.b64 %0, {%1, %2};" : "=l"(q) : "f"(v.x), "f"(v.y));
            sW[i] = q;
        }
        float2* sX2 = (float2*)sX;
        for (int i = tid; i < GEMM_R * (KHALF / 2); i += GEMM_T) {
            int r = i / 25, j = i % 25;
            sX2[r * 25 + j] = x2[(long long)(rowbase + r) * 50 + ph * 25 + j];
        }
        __syncthreads();

        #pragma unroll 2
        for (int k = 0; k < KHALF; k++) {
            unsigned long long w0 = sW[k * 96 + pc * 2];
            unsigned long long w1 = sW[k * 96 + pc * 2 + 1];
            #pragma unroll
            for (int i = 0; i < 8; i++) {
                unsigned long long xx = packdup(sX[(rs + 4 * i) * KHALF + k]);
                acc[i][0] = ffma2(xx, w0, acc[i][0]);
                acc[i][1] = ffma2(xx, w1, acc[i][1]);
            }
        }
    }

    #pragma unroll
    for (int i = 0; i < 8; i++) {
        int r = rowbase + rs + 4 * i;
        float2* o = (float2*)(g_h + (long long)r * HIDDEN);
        o[pc * 2]     = unpack2(acc[i][0]);
        o[pc * 2 + 1] = unpack2(acc[i][1]);
    }
}

// ---------------- 2: attention logits a_src/a_dst (warp per node) ----------------
__global__ void adot_kernel(const float* __restrict__ att_src,
                            const float* __restrict__ att_dst) {
    int lane = threadIdx.x & 31;
    int n = blockIdx.x * (blockDim.x >> 5) + (threadIdx.x >> 5);
    if (n >= N_NODES) return;

    const float2* hp = (const float2*)(g_h + (long long)n * HIDDEN);
    const float2* as2 = (const float2*)att_src;
    const float2* ad2 = (const float2*)att_dst;

    float ps[HEADS], pd[HEADS];
    #pragma unroll
    for (int h = 0; h < HEADS; h++) {
        float2 v = hp[h * 32 + lane];
        float2 a = as2[h * 32 + lane];
        float2 b = ad2[h * 32 + lane];
        ps[h] = v.x * a.x + v.y * a.y;
        pd[h] = v.x * b.x + v.y * b.y;
    }
    #pragma unroll
    for (int d = 16; d > 0; d >>= 1) {
        #pragma unroll
        for (int h = 0; h < HEADS; h++) {
            ps[h] += __shfl_xor_sync(0xFFFFFFFFu, ps[h], d);
            pd[h] += __shfl_xor_sync(0xFFFFFFFFu, pd[h], d);
        }
    }
    if (lane == 0) {
        #pragma unroll
        for (int h = 0; h < HEADS; h++) {
            g_asrc[n * HEADS + h] = ps[h];
            g_adst[n * HEADS + h] = pd[h];
        }
    }
}

// ---------------- 3: degree histogram ----------------
__global__ void hist_kernel(const int* __restrict__ ei) {
    int i = blockIdx.x * blockDim.x + threadIdx.x;
    if (i >= N_EDGES) return;
    atomicAdd(&g_deg[ei[N_EDGES + i]], 1);
}

// ---------------- 4: exclusive scan of deg -> row offsets ----------------
__global__ void scan_blocks() {
    __shared__ int ws[32];
    int tid = threadIdx.x, lane = tid & 31, w = tid >> 5;
    int i = blockIdx.x * 1024 + tid;
    int v = (i < N_NODES) ? g_deg[i] : 0;
    int inc = warp_iscan(v, lane);
    if (lane == 31) ws[w] = inc;
    __syncthreads();
    if (w == 0) ws[lane] = warp_iscan(ws[lane], lane);
    __syncthreads();
    int base = (w > 0) ? ws[w - 1] : 0;
    if (i < N_NODES) g_row[i] = base + inc - v;
    if (tid == 0) g_part[blockIdx.x] = ws[31];
}
__global__ void scan_part() {
    __shared__ int ws[4];
    int t = threadIdx.x, lane = t & 31, w = t >> 5;
    int v = (t < SCAN_NB) ? g_part[t] : 0;
    int inc = warp_iscan(v, lane);
    if (lane == 31) ws[w] = inc;
    __syncthreads();
    if (w == 0 && lane < 4) {
        int s = ws[lane];
        #pragma unroll
        for (int d = 1; d < 4; d <<= 1) {
            int tt = __shfl_up_sync(0x0000000Fu, s, d);
            if (lane >= d) s += tt;
        }
        ws[lane] = s;
    }
    __syncthreads();
    int base = (w > 0) ? ws[w - 1] : 0;
    if (t < SCAN_NB) g_part[t] = base + inc - v;
}
__global__ void scan_add() {
    int i = blockIdx.x * 1024 + threadIdx.x;
    if (i < N_NODES) g_row[i] += g_part[blockIdx.x];
}

// ---- 5: scatter edges into CSR by dst, fused with edge-weight computation ----
// No max-subtraction needed: logits are O(1) (h std ~0.5, att std 0.05),
// exp(e)/sum(exp(e)) == exp(e-m)/sum(exp(e-m)) exactly in math, safely in fp32.
__global__ void scatterw_kernel(const int* __restrict__ ei) {
    int i = blockIdx.x * blockDim.x + threadIdx.x;
    if (i >= N_EDGES) return;
    int s = ei[i];
    int d = ei[N_EDGES + i];
    int pos = g_row[d] + atomicAdd(&g_cur[d], 1);
    float w0 = __expf(lrelu(g_asrc[s * 3 + 0] + g_adst[d * 3 + 0], SLOPE_ATT));
    float w1 = __expf(lrelu(g_asrc[s * 3 + 1] + g_adst[d * 3 + 1], SLOPE_ATT));
    float w2 = __expf(lrelu(g_asrc[s * 3 + 2] + g_adst[d * 3 + 2], SLOPE_ATT));
    g_epack[pos] = make_int4(s, __float_as_int(w0), __float_as_int(w1), __float_as_int(w2));
}

// ---------------- 6: aggregation + block-pooled max (warp per node) ----------------
// 8 warps/block = 8 consecutive nodes; batch is sorted so the block is almost
// always one graph -> pre-reduce pooling into smem, flush once per block.
__global__ __launch_bounds__(256)
void aggregate_kernel(const int* __restrict__ batch,
                      const float* __restrict__ bias) {
    __shared__ unsigned spool[HIDDEN];
    __shared__ int sg0;

    int tid  = threadIdx.x;
    int lane = tid & 31;
    int n = blockIdx.x * 8 + (tid >> 5);     // grid covers exactly N_NODES (12500*8)

    if (tid == 0) sg0 = batch[blockIdx.x * 8];
    if (tid < HIDDEN) spool[tid] = 0u;       // encoded -inf
    __syncthreads();

    int start = g_row[n];
    int deg   = g_deg[n];

    // self-loop weight
    float ws0 = __expf(lrelu(g_asrc[n * 3 + 0] + g_adst[n * 3 + 0], SLOPE_ATT));
    float ws1 = __expf(lrelu(g_asrc[n * 3 + 1] + g_adst[n * 3 + 1], SLOPE_ATT));
    float ws2 = __expf(lrelu(g_asrc[n * 3 + 2] + g_adst[n * 3 + 2], SLOPE_ATT));
    float den0 = ws0, den1 = ws1, den2 = ws2;

    const float2* hp = (const float2*)(g_h + (long long)n * HIDDEN);
    float2 v0 = hp[lane], v1 = hp[32 + lane], v2 = hp[64 + lane];
    float2 a0 = make_float2(ws0 * v0.x, ws0 * v0.y);
    float2 a1 = make_float2(ws1 * v1.x, ws1 * v1.y);
    float2 a2 = make_float2(ws2 * v2.x, ws2 * v2.y);

    const int4* ep = g_epack + start;
    int j = 0;
    for (; j + 2 <= deg; j += 2) {
        int4 e0 = ep[j];
        int4 e1 = ep[j + 1];
        const float2* p0 = (const float2*)(g_h + (long long)e0.x * HIDDEN);
        const float2* p1 = (const float2*)(g_h + (long long)e1.x * HIDDEN);
        float2 u00 = p0[lane], u01 = p0[32 + lane], u02 = p0[64 + lane];
        float2 u10 = p1[lane], u11 = p1[32 + lane], u12 = p1[64 + lane];
        float x00 = __int_as_float(e0.y), x01 = __int_as_float(e0.z), x02 = __int_as_float(e0.w);
        float x10 = __int_as_float(e1.y), x11 = __int_as_float(e1.z), x12 = __int_as_float(e1.w);
        den0 += x00 + x10; den1 += x01 + x11; den2 += x02 + x12;
        a0.x += x00 * u00.x; a0.y += x00 * u00.y;
        a1.x += x01 * u01.x; a1.y += x01 * u01.y;
        a2.x += x02 * u02.x; a2.y += x02 * u02.y;
        a0.x += x10 * u10.x; a0.y += x10 * u10.y;
        a1.x += x11 * u11.x; a1.y += x11 * u11.y;
        a2.x += x12 * u12.x; a2.y += x12 * u12.y;
    }
    if (j < deg) {
        int4 e0 = ep[j];
        const float2* p0 = (const float2*)(g_h + (long long)e0.x * HIDDEN);
        float2 u00 = p0[lane], u01 = p0[32 + lane], u02 = p0[64 + lane];
        float x00 = __int_as_float(e0.y), x01 = __int_as_float(e0.z), x02 = __int_as_float(e0.w);
        den0 += x00; den1 += x01; den2 += x02;
        a0.x += x00 * u00.x; a0.y += x00 * u00.y;
        a1.x += x01 * u01.x; a1.y += x01 * u01.y;
        a2.x += x02 * u02.x; a2.y += x02 * u02.y;
    }

    int g = batch[n];
    const float2* b2 = (const float2*)bias;
    float2 bb0 = b2[lane], bb1 = b2[32 + lane], bb2 = b2[64 + lane];

    float r0 = 1.f / den0, r1 = 1.f / den1, r2 = 1.f / den2;
    unsigned e[6];
    e[0] = enc_f(lrelu(a0.x * r0 + bb0.x, SLOPE_ACT));
    e[1] = enc_f(lrelu(a0.y * r0 + bb0.y, SLOPE_ACT));
    e[2] = enc_f(lrelu(a1.x * r1 + bb1.x, SLOPE_ACT));
    e[3] = enc_f(lrelu(a1.y * r1 + bb1.y, SLOPE_ACT));
    e[4] = enc_f(lrelu(a2.x * r2 + bb2.x, SLOPE_ACT));
    e[5] = enc_f(lrelu(a2.y * r2 + bb2.y, SLOPE_ACT));

    int f0 = lane * 2, f1 = 64 + lane * 2, f2 = 128 + lane * 2;
    if (g == sg0) {
        atomicMax(&spool[f0    ], e[0]); atomicMax(&spool[f0 + 1], e[1]);
        atomicMax(&spool[f1    ], e[2]); atomicMax(&spool[f1 + 1], e[3]);
        atomicMax(&spool[f2    ], e[4]); atomicMax(&spool[f2 + 1], e[5]);
    } else {
        unsigned* pool = g_pool + g * HIDDEN;
        atomicMax(&pool[f0    ], e[0]); atomicMax(&pool[f0 + 1], e[1]);
        atomicMax(&pool[f1    ], e[2]); atomicMax(&pool[f1 + 1], e[3]);
        atomicMax(&pool[f2    ], e[4]); atomicMax(&pool[f2 + 1], e[5]);
    }
    __syncthreads();
    if (tid < HIDDEN) atomicMax(&g_pool[sg0 * HIDDEN + tid], spool[tid]);
}

// ---------------- 7: classifier ----------------
__global__ void classify_kernel(const float* __restrict__ clsW,
                                const float* __restrict__ clsb,
                                float* __restrict__ out) {
    int t = threadIdx.x;
    if (t >= NUM_GRAPHS * NUM_CLASSES) return;
    int g = t >> 1, c = t & 1;
    float s = clsb[c];
    #pragma unroll 4
    for (int k = 0; k < HIDDEN; k++)
        s += dec_f(g_pool[g * HIDDEN + k]) * clsW[k * NUM_CLASSES + c];
    out[g * NUM_CLASSES + c] = s;
}

// ---------------- launch ----------------
extern "C" void kernel_launch(void* const* d_in, const int* in_sizes, int n_in,
                              void* d_out, int out_size) {
    const float* x       = (const float*)d_in[0];
    const int*   ei      = (const int*)d_in[1];     // int32 (JAX x64 disabled)
    const int*   batch   = (const int*)d_in[2];     // int32
    const float* W       = (const float*)d_in[3];
    const float* att_src = (const float*)d_in[4];
    const float* att_dst = (const float*)d_in[5];
    const float* bias    = (const float*)d_in[6];
    const float* clsW    = (const float*)d_in[7];
    const float* clsb    = (const float*)d_in[8];
    float* out = (float*)d_out;

    init_kernel<<<256, 256>>>();
    hist_kernel<<<(N_EDGES + 255) / 256, 256>>>(ei);
    scan_blocks<<<SCAN_NB, 1024>>>();
    scan_part<<<1, 128>>>();
    scan_add<<<SCAN_NB, 1024>>>();
    gemm_kernel<<<N_NODES / GEMM_R, GEMM_T>>>(x, W);
    adot_kernel<<<(N_NODES + 7) / 8, 256>>>(att_src, att_dst);
    scatterw_kernel<<<(N_EDGES + 255) / 256, 256>>>(ei);
    aggregate_kernel<<<N_NODES / 8, 256>>>(batch, bias);
    classify_kernel<<<1, 256>>>(clsW, clsb, out);
}

// round 12
// speedup vs baseline: 1.4779x; 1.1525x over previous
#include <cuda_runtime.h>
#include <cuda_bf16.h>

#define N_NODES    100000
#define N_EDGES    1600000
#define F_IN       100
#define HEADS      3
#define HEAD_DIM   64
#define HIDDEN     192
#define NUM_GRAPHS 128
#define NUM_CLASSES 2
#define SLOPE_ATT  0.2f
#define SLOPE_ACT  0.01f

#define SCAN_NB    ((N_NODES + 1023) / 1024)   // 98
#define HWORDS     96                          // bf16x2 words per node row

// ---------------- scratch (static __device__: allocation-free) ----------------
__device__ unsigned     g_hb[N_NODES * HWORDS];       // h in bf16x2, 38.4 MB
__device__ float        g_asrc[N_NODES * HEADS];
__device__ float        g_adst[N_NODES * HEADS];
__device__ int          g_deg[N_NODES];
__device__ int          g_row[N_NODES];               // per-block exclusive scan
__device__ int          g_cur[N_NODES];
__device__ int4         g_epack[N_EDGES];             // CSR: {src, w0,w1,w2 bits}
__device__ unsigned     g_pool[NUM_GRAPHS * HIDDEN];  // encoded-float max
__device__ int          g_part[128];                  // scan block offsets

// ---------------- helpers ----------------
__device__ __forceinline__ float lrelu(float x, float s) { return x > 0.f ? x : s * x; }

__device__ __forceinline__ unsigned enc_f(float f) {
    unsigned b = __float_as_uint(f);
    return (b & 0x80000000u) ? ~b : (b | 0x80000000u);
}
__device__ __forceinline__ float dec_f(unsigned k) {
    unsigned b = (k & 0x80000000u) ? (k & 0x7FFFFFFFu) : ~k;
    return __uint_as_float(b);
}

// bf16x2 word -> two exact fp32 (bf16 is truncated fp32: just shift)
__device__ __forceinline__ float blo(unsigned q) { return __uint_as_float(q << 16); }
__device__ __forceinline__ float bhi(unsigned q) { return __uint_as_float(q & 0xFFFF0000u); }

// pack two fp32 -> bf16x2 word (lo = x, hi = y), round-to-nearest
__device__ __forceinline__ unsigned pack_bf(float x, float y) {
    unsigned w;
    asm("cvt.rn.bf16x2.f32 %0, %1, %2;" : "=r"(w) : "f"(y), "f"(x));
    return w;
}

// packed f32x2 FMA (Blackwell PTX-only; 2x fp32 throughput)
__device__ __forceinline__ unsigned long long ffma2(unsigned long long a,
                                                    unsigned long long b,
                                                    unsigned long long c) {
    unsigned long long d;
    asm("fma.rn.f32x2 %0, %1, %2, %3;" : "=l"(d) : "l"(a), "l"(b), "l"(c));
    return d;
}
__device__ __forceinline__ unsigned long long packdup(float x) {
    unsigned long long r;
    asm("mov.b64 %0, {%1, %1};" : "=l"(r) : "f"(x));
    return r;
}
__device__ __forceinline__ float2 unpack2(unsigned long long v) {
    float2 r;
    asm("mov.b64 {%0, %1}, %2;" : "=f"(r.x), "=f"(r.y) : "l"(v));
    return r;
}

__device__ __forceinline__ int warp_iscan(int v, int lane) {
    #pragma unroll
    for (int d = 1; d < 32; d <<= 1) {
        int t = __shfl_up_sync(0xFFFFFFFFu, v, d);
        if (lane >= d) v += t;
    }
    return v;
}

// ---------------- 0: init scratch ----------------
__global__ void init_kernel() {
    int stride = gridDim.x * blockDim.x;
    for (int i = blockIdx.x * blockDim.x + threadIdx.x; i < N_NODES; i += stride) {
        g_deg[i] = 0;
        g_cur[i] = 0;
    }
    for (int i = blockIdx.x * blockDim.x + threadIdx.x; i < NUM_GRAPHS * HIDDEN; i += stride)
        g_pool[i] = 0u;   // encodes "most negative"
}

// ---------------- 1: h = x @ W  (fp32 math, bf16x2 store) ----------------
#define GEMM_T 192
#define GEMM_R 32
#define KHALF  50
__global__ __launch_bounds__(GEMM_T)
void gemm_kernel(const float* __restrict__ x, const float* __restrict__ W) {
    __shared__ unsigned long long sW[KHALF * 96];   // 38400 B
    __shared__ float sX[GEMM_R * KHALF];            //  6400 B

    int tid = threadIdx.x;
    int rowbase = blockIdx.x * GEMM_R;
    int rs = tid & 3;           // row slot 0..3 -> rows rs + 4i
    int pc = tid >> 2;          // pair-group 0..47 -> pairs pc*2, pc*2+1

    unsigned long long acc[8][2];
    #pragma unroll
    for (int i = 0; i < 8; i++) { acc[i][0] = 0ull; acc[i][1] = 0ull; }

    const float2* W2 = (const float2*)W;   // [100][96] pairs
    const float2* x2 = (const float2*)x;

    #pragma unroll 1
    for (int ph = 0; ph < 2; ph++) {
        int k0 = ph * KHALF;
        __syncthreads();
        for (int i = tid; i < KHALF * 96; i += GEMM_T) {
            int k = i / 96, p = i % 96;
            float2 v = W2[(k0 + k) * 96 + p];
            unsigned long long q;
            asm("mov.b64 %0, {%1, %2};" : "=l"(q) : "f"(v.x), "f"(v.y));
            sW[i] = q;
        }
        float2* sX2 = (float2*)sX;
        for (int i = tid; i < GEMM_R * (KHALF / 2); i += GEMM_T) {
            int r = i / 25, j = i % 25;
            sX2[r * 25 + j] = x2[(long long)(rowbase + r) * 50 + ph * 25 + j];
        }
        __syncthreads();

        #pragma unroll 2
        for (int k = 0; k < KHALF; k++) {
            unsigned long long w0 = sW[k * 96 + pc * 2];
            unsigned long long w1 = sW[k * 96 + pc * 2 + 1];
            #pragma unroll
            for (int i = 0; i < 8; i++) {
                unsigned long long xx = packdup(sX[(rs + 4 * i) * KHALF + k]);
                acc[i][0] = ffma2(xx, w0, acc[i][0]);
                acc[i][1] = ffma2(xx, w1, acc[i][1]);
            }
        }
    }

    #pragma unroll
    for (int i = 0; i < 8; i++) {
        int r = rowbase + rs + 4 * i;
        float2 a = unpack2(acc[i][0]);
        float2 b = unpack2(acc[i][1]);
        uint2* o = (uint2*)(g_hb + (long long)r * HWORDS) + pc;
        uint2 w;
        w.x = pack_bf(a.x, a.y);
        w.y = pack_bf(b.x, b.y);
        *o = w;
    }
}

// ---------------- 2: attention logits a_src/a_dst (warp per node) ----------------
__global__ void adot_kernel(const float* __restrict__ att_src,
                            const float* __restrict__ att_dst) {
    int lane = threadIdx.x & 31;
    int n = blockIdx.x * (blockDim.x >> 5) + (threadIdx.x >> 5);
    if (n >= N_NODES) return;

    const unsigned* hp = g_hb + (long long)n * HWORDS;
    const float2* as2 = (const float2*)att_src;
    const float2* ad2 = (const float2*)att_dst;

    float ps[HEADS], pd[HEADS];
    #pragma unroll
    for (int h = 0; h < HEADS; h++) {
        unsigned q = hp[h * 32 + lane];
        float vx = blo(q), vy = bhi(q);
        float2 a = as2[h * 32 + lane];
        float2 b = ad2[h * 32 + lane];
        ps[h] = vx * a.x + vy * a.y;
        pd[h] = vx * b.x + vy * b.y;
    }
    #pragma unroll
    for (int d = 16; d > 0; d >>= 1) {
        #pragma unroll
        for (int h = 0; h < HEADS; h++) {
            ps[h] += __shfl_xor_sync(0xFFFFFFFFu, ps[h], d);
            pd[h] += __shfl_xor_sync(0xFFFFFFFFu, pd[h], d);
        }
    }
    if (lane == 0) {
        #pragma unroll
        for (int h = 0; h < HEADS; h++) {
            g_asrc[n * HEADS + h] = ps[h];
            g_adst[n * HEADS + h] = pd[h];
        }
    }
}

// ---------------- 3: degree histogram ----------------
__global__ void hist_kernel(const int* __restrict__ ei) {
    int i = blockIdx.x * blockDim.x + threadIdx.x;
    if (i >= N_EDGES) return;
    atomicAdd(&g_deg[ei[N_EDGES + i]], 1);
}

// ---------------- 4: two-level exclusive scan (scan_add folded into consumers) --
__global__ void scan_blocks() {
    __shared__ int ws[32];
    int tid = threadIdx.x, lane = tid & 31, w = tid >> 5;
    int i = blockIdx.x * 1024 + tid;
    int v = (i < N_NODES) ? g_deg[i] : 0;
    int inc = warp_iscan(v, lane);
    if (lane == 31) ws[w] = inc;
    __syncthreads();
    if (w == 0) ws[lane] = warp_iscan(ws[lane], lane);
    __syncthreads();
    int base = (w > 0) ? ws[w - 1] : 0;
    if (i < N_NODES) g_row[i] = base + inc - v;
    if (tid == 0) g_part[blockIdx.x] = ws[31];
}
__global__ void scan_part() {
    __shared__ int ws[4];
    int t = threadIdx.x, lane = t & 31, w = t >> 5;
    int v = (t < SCAN_NB) ? g_part[t] : 0;
    int inc = warp_iscan(v, lane);
    if (lane == 31) ws[w] = inc;
    __syncthreads();
    if (w == 0 && lane < 4) {
        int s = ws[lane];
        #pragma unroll
        for (int d = 1; d < 4; d <<= 1) {
            int tt = __shfl_up_sync(0x0000000Fu, s, d);
            if (lane >= d) s += tt;
        }
        ws[lane] = s;
    }
    __syncthreads();
    int base = (w > 0) ? ws[w - 1] : 0;
    if (t < SCAN_NB) g_part[t] = base + inc - v;
}

// ---- 5: scatter edges into CSR by dst, fused with edge-weight computation ----
__global__ void scatterw_kernel(const int* __restrict__ ei) {
    int i = blockIdx.x * blockDim.x + threadIdx.x;
    if (i >= N_EDGES) return;
    int s = ei[i];
    int d = ei[N_EDGES + i];
    int pos = g_row[d] + g_part[d >> 10] + atomicAdd(&g_cur[d], 1);
    float w0 = __expf(lrelu(g_asrc[s * 3 + 0] + g_adst[d * 3 + 0], SLOPE_ATT));
    float w1 = __expf(lrelu(g_asrc[s * 3 + 1] + g_adst[d * 3 + 1], SLOPE_ATT));
    float w2 = __expf(lrelu(g_asrc[s * 3 + 2] + g_adst[d * 3 + 2], SLOPE_ATT));
    g_epack[pos] = make_int4(s, __float_as_int(w0), __float_as_int(w1), __float_as_int(w2));
}

// ---------------- 6: aggregation (bf16 gather) + block-pooled max ----------------
__global__ __launch_bounds__(256)
void aggregate_kernel(const int* __restrict__ batch,
                      const float* __restrict__ bias) {
    __shared__ unsigned spool[HIDDEN];
    __shared__ int sg0;

    int tid  = threadIdx.x;
    int lane = tid & 31;
    int n = blockIdx.x * 8 + (tid >> 5);     // grid covers exactly N_NODES (12500*8)

    if (tid == 0) sg0 = batch[blockIdx.x * 8];
    if (tid < HIDDEN) spool[tid] = 0u;       // encoded -inf
    __syncthreads();

    int start = g_row[n] + g_part[n >> 10];
    int deg   = g_deg[n];

    // self-loop weight
    float ws0 = __expf(lrelu(g_asrc[n * 3 + 0] + g_adst[n * 3 + 0], SLOPE_ATT));
    float ws1 = __expf(lrelu(g_asrc[n * 3 + 1] + g_adst[n * 3 + 1], SLOPE_ATT));
    float ws2 = __expf(lrelu(g_asrc[n * 3 + 2] + g_adst[n * 3 + 2], SLOPE_ATT));
    float den0 = ws0, den1 = ws1, den2 = ws2;

    const unsigned* hp = g_hb + (long long)n * HWORDS;
    unsigned qs0 = hp[lane], qs1 = hp[32 + lane], qs2 = hp[64 + lane];
    float2 a0 = make_float2(ws0 * blo(qs0), ws0 * bhi(qs0));
    float2 a1 = make_float2(ws1 * blo(qs1), ws1 * bhi(qs1));
    float2 a2 = make_float2(ws2 * blo(qs2), ws2 * bhi(qs2));

    const int4* ep = g_epack + start;
    int j = 0;
    for (; j + 2 <= deg; j += 2) {
        int4 e0 = ep[j];
        int4 e1 = ep[j + 1];
        const unsigned* p0 = g_hb + (long long)e0.x * HWORDS;
        const unsigned* p1 = g_hb + (long long)e1.x * HWORDS;
        unsigned q00 = p0[lane], q01 = p0[32 + lane], q02 = p0[64 + lane];
        unsigned q10 = p1[lane], q11 = p1[32 + lane], q12 = p1[64 + lane];
        float x00 = __int_as_float(e0.y), x01 = __int_as_float(e0.z), x02 = __int_as_float(e0.w);
        float x10 = __int_as_float(e1.y), x11 = __int_as_float(e1.z), x12 = __int_as_float(e1.w);
        den0 += x00 + x10; den1 += x01 + x11; den2 += x02 + x12;
        a0.x += x00 * blo(q00); a0.y += x00 * bhi(q00);
        a1.x += x01 * blo(q01); a1.y += x01 * bhi(q01);
        a2.x += x02 * blo(q02); a2.y += x02 * bhi(q02);
        a0.x += x10 * blo(q10); a0.y += x10 * bhi(q10);
        a1.x += x11 * blo(q11); a1.y += x11 * bhi(q11);
        a2.x += x12 * blo(q12); a2.y += x12 * bhi(q12);
    }
    if (j < deg) {
        int4 e0 = ep[j];
        const unsigned* p0 = g_hb + (long long)e0.x * HWORDS;
        unsigned q00 = p0[lane], q01 = p0[32 + lane], q02 = p0[64 + lane];
        float x00 = __int_as_float(e0.y), x01 = __int_as_float(e0.z), x02 = __int_as_float(e0.w);
        den0 += x00; den1 += x01; den2 += x02;
        a0.x += x00 * blo(q00); a0.y += x00 * bhi(q00);
        a1.x += x01 * blo(q01); a1.y += x01 * bhi(q01);
        a2.x += x02 * blo(q02); a2.y += x02 * bhi(q02);
    }

    int g = batch[n];
    const float2* b2 = (const float2*)bias;
    float2 bb0 = b2[lane], bb1 = b2[32 + lane], bb2 = b2[64 + lane];

    float r0 = 1.f / den0, r1 = 1.f / den1, r2 = 1.f / den2;
    unsigned e[6];
    e[0] = enc_f(lrelu(a0.x * r0 + bb0.x, SLOPE_ACT));
    e[1] = enc_f(lrelu(a0.y * r0 + bb0.y, SLOPE_ACT));
    e[2] = enc_f(lrelu(a1.x * r1 + bb1.x, SLOPE_ACT));
    e[3] = enc_f(lrelu(a1.y * r1 + bb1.y, SLOPE_ACT));
    e[4] = enc_f(lrelu(a2.x * r2 + bb2.x, SLOPE_ACT));
    e[5] = enc_f(lrelu(a2.y * r2 + bb2.y, SLOPE_ACT));

    int f0 = lane * 2, f1 = 64 + lane * 2, f2 = 128 + lane * 2;
    if (g == sg0) {
        atomicMax(&spool[f0    ], e[0]); atomicMax(&spool[f0 + 1], e[1]);
        atomicMax(&spool[f1    ], e[2]); atomicMax(&spool[f1 + 1], e[3]);
        atomicMax(&spool[f2    ], e[4]); atomicMax(&spool[f2 + 1], e[5]);
    } else {
        unsigned* pool = g_pool + g * HIDDEN;
        atomicMax(&pool[f0    ], e[0]); atomicMax(&pool[f0 + 1], e[1]);
        atomicMax(&pool[f1    ], e[2]); atomicMax(&pool[f1 + 1], e[3]);
        atomicMax(&pool[f2    ], e[4]); atomicMax(&pool[f2 + 1], e[5]);
    }
    __syncthreads();
    if (tid < HIDDEN) atomicMax(&g_pool[sg0 * HIDDEN + tid], spool[tid]);
}

// ---------------- 7: classifier ----------------
__global__ void classify_kernel(const float* __restrict__ clsW,
                                const float* __restrict__ clsb,
                                float* __restrict__ out) {
    int t = threadIdx.x;
    if (t >= NUM_GRAPHS * NUM_CLASSES) return;
    int g = t >> 1, c = t & 1;
    float s = clsb[c];
    #pragma unroll 4
    for (int k = 0; k < HIDDEN; k++)
        s += dec_f(g_pool[g * HIDDEN + k]) * clsW[k * NUM_CLASSES + c];
    out[g * NUM_CLASSES + c] = s;
}

// ---------------- launch ----------------
extern "C" void kernel_launch(void* const* d_in, const int* in_sizes, int n_in,
                              void* d_out, int out_size) {
    const float* x       = (const float*)d_in[0];
    const int*   ei      = (const int*)d_in[1];     // int32 (JAX x64 disabled)
    const int*   batch   = (const int*)d_in[2];     // int32
    const float* W       = (const float*)d_in[3];
    const float* att_src = (const float*)d_in[4];
    const float* att_dst = (const float*)d_in[5];
    const float* bias    = (const float*)d_in[6];
    const float* clsW    = (const float*)d_in[7];
    const float* clsb    = (const float*)d_in[8];
    float* out = (float*)d_out;

    init_kernel<<<256, 256>>>();
    hist_kernel<<<(N_EDGES + 255) / 256, 256>>>(ei);
    scan_blocks<<<SCAN_NB, 1024>>>();
    scan_part<<<1, 128>>>();
    gemm_kernel<<<N_NODES / GEMM_R, GEMM_T>>>(x, W);
    adot_kernel<<<(N_NODES + 7) / 8, 256>>>(att_src, att_dst);
    scatterw_kernel<<<(N_EDGES + 255) / 256, 256>>>(ei);
    aggregate_kernel<<<N_NODES / 8, 256>>>(batch, bias);
    classify_kernel<<<1, 256>>>(clsW, clsb, out);
}